// round 8
// baseline (speedup 1.0000x reference)
#include <cuda_runtime.h>
#include <cuda_bf16.h>
#include <cstdint>

#define NN      50000
#define NE      800000
#define NRELS   200
#define NB_SCAN 98          // ceil(NN / 512)

// -------- scratch (device globals; allocation is forbidden) --------
__device__ int          g_cnt[NN];           // dst degree (re-zeroed by k_agg each call)
__device__ int          g_off[NN];           // per-512-block local exclusive offsets; scatter advances to local end
__device__ int          g_bsum[NB_SCAN];     // per-block totals
__device__ int          g_boff[NB_SCAN];     // exclusive scan of block totals
__device__ unsigned int g_key[NE];           // (src | etype<<16) sorted by dst
__device__ float        g_rr[NRELS * 128];   // interleaved (rel, relB) per relation
__device__ float        g_A[NN * 64];        // (sum h)/cnt
__device__ float        g_B[NN * 64];        // (sum h*r)/cnt
__device__ float        g_C[NN * 64];        // (sum relB)/cnt

// -------- f32x2 helpers --------
#define FMA2(acc, a, b) \
    asm("fma.rn.f32x2 %0, %1, %2, %0;" : "+l"(acc) : "l"(a), "l"(b))
#define PACK_DUP(h2, h) \
    asm("mov.b64 %0, {%1, %1};" : "=l"(h2) : "f"(h))
#define UNPACK2(lo, hi, v) \
    asm("mov.b64 {%0, %1}, %2;" : "=f"(lo), "=f"(hi) : "l"(v))

// -------- K1: fused dst-degree histogram + relB table --------
__global__ __launch_bounds__(256) void k_fused(const float* __restrict__ rel,
                                               const float* __restrict__ Wn,
                                               const int* __restrict__ dst, int E) {
    int b = blockIdx.x, tid = threadIdx.x;

    if (b < NRELS && tid < 64) {
        int t = b, j = tid;
        float s = 0.0f;
        #pragma unroll 8
        for (int k = 0; k < 64; k++)
            s += rel[t * 64 + k] * (Wn[k * 64 + j] + Wn[(192 + k) * 64 + j]);
        int base = t * 128 + (j >> 1) * 4 + (j & 1);
        g_rr[base]     = rel[t * 64 + j];   // rel at float4 slots .x/.y
        g_rr[base + 2] = s;                 // relB at slots .z/.w
    }

    int i = b * 256 + tid;
    int stride = gridDim.x * 256;
    int n4 = E >> 2;
    const int4* d4 = (const int4*)dst;
    for (int j = i; j < n4; j += stride) {
        int4 v = d4[j];
        atomicAdd(&g_cnt[v.x], 1);
        atomicAdd(&g_cnt[v.y], 1);
        atomicAdd(&g_cnt[v.z], 1);
        atomicAdd(&g_cnt[v.w], 1);
    }
    if (i < (E & 3)) atomicAdd(&g_cnt[dst[(n4 << 2) + i]], 1);
}

// -------- K2a: per-512-block exclusive scan (coalesced; measured-fast shape) --------
__global__ __launch_bounds__(512) void kscanA() {
    __shared__ int tmp[512];
    int b = blockIdx.x, tid = threadIdx.x;
    int i = b * 512 + tid;
    int v = (i < NN) ? g_cnt[i] : 0;
    tmp[tid] = v;
    __syncthreads();
    #pragma unroll
    for (int d = 1; d < 512; d <<= 1) {
        int t = (tid >= d) ? tmp[tid - d] : 0;
        __syncthreads();
        tmp[tid] += t;
        __syncthreads();
    }
    if (i < NN) g_off[i] = tmp[tid] - v;     // local exclusive offset
    if (tid == 511) g_bsum[b] = tmp[511];
}

// -------- K2b: scan the 98 block sums --------
__global__ __launch_bounds__(128) void kscanB() {
    __shared__ int tmp[128];
    int tid = threadIdx.x;
    int v = (tid < NB_SCAN) ? g_bsum[tid] : 0;
    tmp[tid] = v;
    __syncthreads();
    #pragma unroll
    for (int d = 1; d < 128; d <<= 1) {
        int t = (tid >= d) ? tmp[tid - d] : 0;
        __syncthreads();
        tmp[tid] += t;
        __syncthreads();
    }
    if (tid < NB_SCAN) g_boff[tid] = tmp[tid] - v;
}

// -------- K3: counting-sort scatter by dst (global pos = local + block offset) --------
__global__ void k_scatter(const int* __restrict__ src, const int* __restrict__ dst,
                          const int* __restrict__ et, int E) {
    int i = blockIdx.x * blockDim.x + threadIdx.x;
    int stride = gridDim.x * blockDim.x;
    int n4 = E >> 2;
    const int4* s4 = (const int4*)src;
    const int4* d4 = (const int4*)dst;
    const int4* t4 = (const int4*)et;
    for (int j = i; j < n4; j += stride) {
        int4 s = s4[j];
        int4 d = d4[j];
        int4 t = t4[j];
        int p0 = atomicAdd(&g_off[d.x], 1) + g_boff[d.x >> 9];
        int p1 = atomicAdd(&g_off[d.y], 1) + g_boff[d.y >> 9];
        int p2 = atomicAdd(&g_off[d.z], 1) + g_boff[d.z >> 9];
        int p3 = atomicAdd(&g_off[d.w], 1) + g_boff[d.w >> 9];
        g_key[p0] = (unsigned)s.x | ((unsigned)t.x << 16);
        g_key[p1] = (unsigned)s.y | ((unsigned)t.y << 16);
        g_key[p2] = (unsigned)s.z | ((unsigned)t.z << 16);
        g_key[p3] = (unsigned)s.w | ((unsigned)t.w << 16);
    }
    if (i < (E & 3)) {
        int e = (n4 << 2) + i;
        int d = dst[e];
        int p = atomicAdd(&g_off[d], 1) + g_boff[d >> 9];
        g_key[p] = (unsigned)src[e] | ((unsigned)et[e] << 16);
    }
}

// -------- K4: per-dst aggregation (R6 measured shape: warp/node, 1 edge/iter) --------
__global__ __launch_bounds__(256) void k_agg(const float* __restrict__ feat) {
    int w = (blockIdx.x * 256 + threadIdx.x) >> 5;
    if (w >= NN) return;
    int lane = threadIdx.x & 31;
    // after scatter, g_off[j] == local segment end; global end = + g_boff[j>>9]
    int end = g_off[w] + g_boff[w >> 9];
    int beg = w ? (g_off[w - 1] + g_boff[(w - 1) >> 9]) : 0;
    if (lane == 0) g_cnt[w] = 0;      // re-zero for next replay (deterministic)

    const float2* f2  = (const float2*)feat;
    const float4* rr4 = (const float4*)g_rr;

    float ax = 0.f, ay = 0.f, bx = 0.f, by = 0.f, cx = 0.f, cy = 0.f;

    if (beg < end) {
        unsigned k = g_key[beg];
        for (int i = beg; i < end; i++) {
            unsigned kn = (i + 1 < end) ? g_key[i + 1] : k;   // 1-ahead key prefetch
            float2 h = f2[(k & 0xffffu) * 32 + lane];
            float4 q = rr4[(k >> 16) * 32 + lane];
            ax += h.x;  ay += h.y;
            bx = fmaf(h.x, q.x, bx);
            by = fmaf(h.y, q.y, by);
            cx += q.z;  cy += q.w;
            k = kn;
        }
    }
    float inv = 1.0f / fmaxf((float)(end - beg), 1.0f);
    int o = w * 32 + lane;
    ((float2*)g_A)[o] = make_float2(ax * inv, ay * inv);
    ((float2*)g_B)[o] = make_float2(bx * inv, by * inv);
    ((float2*)g_C)[o] = make_float2(cx * inv, cy * inv);
}

// -------- K5: out = A@W13 + B@W2 + C + feat@LW  (32 nodes / block, 256 thr) --------
#define TS 65
#define FSMEM ((3 * 4096 + 3 * 32 * TS) * 4)

__global__ __launch_bounds__(256) void k_final(const float* __restrict__ feat,
                                               const float* __restrict__ Wn,
                                               const float* __restrict__ LW,
                                               float* __restrict__ out, int N) {
    extern __shared__ float smem[];
    float* W13s = smem;                 // 4096
    float* W2s  = smem + 4096;          // 4096
    float* LWs  = smem + 8192;          // 4096
    float* As   = smem + 12288;         // 32*65
    float* Bs   = As + 32 * TS;
    float* Fs   = Bs + 32 * TS;

    int tid = threadIdx.x;
    for (int idx = tid; idx < 4096; idx += 256) {
        W13s[idx] = Wn[idx] + Wn[8192 + idx];
        W2s[idx]  = Wn[4096 + idx];
        LWs[idx]  = LW[idx];
    }

    int n0 = blockIdx.x * 32;
    #pragma unroll
    for (int p = 0; p < 6; p++) {
        int idx = p * 256 + tid;        // 0..1535 : matrix = idx/512, slot = idx%512
        int mat = idx >> 9;
        int slot = idx & 511;
        int e = slot >> 4, c4 = slot & 15;
        int node = n0 + e;
        const float* srcp = (mat == 0) ? g_A : (mat == 1) ? g_B : feat;
        float* dstp = (mat == 0) ? As : (mat == 1) ? Bs : Fs;
        float4 v = make_float4(0.f, 0.f, 0.f, 0.f);
        if (node < N) v = *(const float4*)&srcp[(size_t)node * 64 + c4 * 4];
        float* hp = &dstp[e * TS + c4 * 4];
        hp[0] = v.x; hp[1] = v.y; hp[2] = v.z; hp[3] = v.w;
    }
    __syncthreads();

    int ty = tid >> 3, tx = tid & 7, jj = tx * 8;
    int node = n0 + ty;

    unsigned long long a0 = 0, a1 = 0, a2 = 0, a3 = 0;
    #pragma unroll 4
    for (int k = 0; k < 64; k++) {
        float la = As[ty * TS + k];
        float lb = Bs[ty * TS + k];
        float lf = Fs[ty * TS + k];
        unsigned long long la2, lb2, lf2;
        PACK_DUP(la2, la); PACK_DUP(lb2, lb); PACK_DUP(lf2, lf);

        const float* w13 = &W13s[(k << 6) + jj];
        const float* w2  = &W2s[(k << 6) + jj];
        const float* lw  = &LWs[(k << 6) + jj];
        ulonglong2 wA = *reinterpret_cast<const ulonglong2*>(w13);
        ulonglong2 wB = *reinterpret_cast<const ulonglong2*>(w13 + 4);
        ulonglong2 vA = *reinterpret_cast<const ulonglong2*>(w2);
        ulonglong2 vB = *reinterpret_cast<const ulonglong2*>(w2 + 4);
        ulonglong2 uA = *reinterpret_cast<const ulonglong2*>(lw);
        ulonglong2 uB = *reinterpret_cast<const ulonglong2*>(lw + 4);

        FMA2(a0, la2, wA.x); FMA2(a1, la2, wA.y); FMA2(a2, la2, wB.x); FMA2(a3, la2, wB.y);
        FMA2(a0, lb2, vA.x); FMA2(a1, lb2, vA.y); FMA2(a2, lb2, vB.x); FMA2(a3, lb2, vB.y);
        FMA2(a0, lf2, uA.x); FMA2(a1, lf2, uA.y); FMA2(a2, lf2, uB.x); FMA2(a3, lf2, uB.y);
    }

    if (node < N) {
        float4 c0 = *(const float4*)&g_C[(size_t)node * 64 + jj];
        float4 c1 = *(const float4*)&g_C[(size_t)node * 64 + jj + 4];
        float v0, v1, v2, v3, v4, v5, v6, v7;
        UNPACK2(v0, v1, a0); UNPACK2(v2, v3, a1);
        UNPACK2(v4, v5, a2); UNPACK2(v6, v7, a3);
        float* p = out + (size_t)node * 64 + jj;
        *(float4*)p       = make_float4(v0 + c0.x, v1 + c0.y, v2 + c0.z, v3 + c0.w);
        *(float4*)(p + 4) = make_float4(v4 + c1.x, v5 + c1.y, v6 + c1.z, v7 + c1.w);
    }
}

// -------- launch --------
extern "C" void kernel_launch(void* const* d_in, const int* in_sizes, int n_in,
                              void* d_out, int out_size) {
    const float* feat = (const float*)d_in[0];
    const float* rel  = (const float*)d_in[1];
    const float* Wn   = (const float*)d_in[2];
    const float* LW   = (const float*)d_in[3];
    const int*   src  = (const int*)d_in[4];
    const int*   dst  = (const int*)d_in[5];
    const int*   et   = (const int*)d_in[6];
    float* out = (float*)d_out;

    int E = in_sizes[4];
    int N = in_sizes[0] / 64;

    cudaFuncSetAttribute(k_final, cudaFuncAttributeMaxDynamicSharedMemorySize, FSMEM);

    k_fused<<<512, 256>>>(rel, Wn, dst, E);          // 0
    kscanA<<<NB_SCAN, 512>>>();                       // 1
    kscanB<<<1, 128>>>();                             // 2
    k_scatter<<<800, 256>>>(src, dst, et, E);         // 3  <- ncu capture slot
    k_agg<<<(NN * 32 + 255) / 256, 256>>>(feat);      // 4
    k_final<<<(N + 31) / 32, 256, FSMEM>>>(feat, Wn, LW, out, N);
}

// round 9
// speedup vs baseline: 1.5740x; 1.5740x over previous
#include <cuda_runtime.h>
#include <cuda_bf16.h>
#include <cstdint>

#define NN      50000
#define NE      800000
#define NRELS   200
#define NB_SCAN 98          // ceil(NN / 512)

// -------- scratch (device globals; allocation is forbidden) --------
__device__ int          g_cnt[NN];           // dst degree (re-zeroed by k_agg each call)
__device__ int          g_off[NN + 1];       // global exclusive offsets (kscanC), stable
__device__ int          g_cur[NN];           // scatter cursors (consumed each call)
__device__ int          g_bsum[NB_SCAN];
__device__ int          g_boff[NB_SCAN];
__device__ unsigned int g_key[NE];           // (src | etype<<16) sorted by dst
__device__ float        g_rr[NRELS * 128];   // interleaved (rel, relB) per relation
__device__ float        g_A[NN * 64];        // (sum h)/cnt
__device__ float        g_B[NN * 64];        // (sum h*r)/cnt
__device__ float        g_C[NN * 64];        // (sum relB)/cnt

// -------- f32x2 helpers --------
#define FMA2(acc, a, b) \
    asm("fma.rn.f32x2 %0, %1, %2, %0;" : "+l"(acc) : "l"(a), "l"(b))
#define PACK_DUP(h2, h) \
    asm("mov.b64 %0, {%1, %1};" : "=l"(h2) : "f"(h))
#define UNPACK2(lo, hi, v) \
    asm("mov.b64 {%0, %1}, %2;" : "=f"(lo), "=f"(hi) : "l"(v))

// -------- K1: fused dst-degree histogram + relB table --------
__global__ __launch_bounds__(256) void k_fused(const float* __restrict__ rel,
                                               const float* __restrict__ Wn,
                                               const int* __restrict__ dst, int E) {
    int b = blockIdx.x, tid = threadIdx.x;

    if (b < NRELS && tid < 64) {
        int t = b, j = tid;
        float s = 0.0f;
        #pragma unroll 8
        for (int k = 0; k < 64; k++)
            s += rel[t * 64 + k] * (Wn[k * 64 + j] + Wn[(192 + k) * 64 + j]);
        int base = t * 128 + (j >> 1) * 4 + (j & 1);
        g_rr[base]     = rel[t * 64 + j];   // rel at float4 slots .x/.y
        g_rr[base + 2] = s;                 // relB at slots .z/.w
    }

    int i = b * 256 + tid;
    int stride = gridDim.x * 256;
    int n4 = E >> 2;
    const int4* d4 = (const int4*)dst;
    for (int j = i; j < n4; j += stride) {
        int4 v = d4[j];
        atomicAdd(&g_cnt[v.x], 1);
        atomicAdd(&g_cnt[v.y], 1);
        atomicAdd(&g_cnt[v.z], 1);
        atomicAdd(&g_cnt[v.w], 1);
    }
    if (i < (E & 3)) atomicAdd(&g_cnt[dst[(n4 << 2) + i]], 1);
}

// -------- K2a: per-512-block exclusive scan (R3-measured shape) --------
__global__ __launch_bounds__(512) void kscanA() {
    __shared__ int tmp[512];
    int b = blockIdx.x, tid = threadIdx.x;
    int i = b * 512 + tid;
    int v = (i < NN) ? g_cnt[i] : 0;
    tmp[tid] = v;
    __syncthreads();
    #pragma unroll
    for (int d = 1; d < 512; d <<= 1) {
        int t = (tid >= d) ? tmp[tid - d] : 0;
        __syncthreads();
        tmp[tid] += t;
        __syncthreads();
    }
    if (i < NN) g_off[i] = tmp[tid] - v;     // local exclusive, globalized by kscanC
    if (tid == 511) g_bsum[b] = tmp[511];
}

// -------- K2b: scan the 98 block sums --------
__global__ __launch_bounds__(128) void kscanB() {
    __shared__ int tmp[128];
    int tid = threadIdx.x;
    int v = (tid < NB_SCAN) ? g_bsum[tid] : 0;
    tmp[tid] = v;
    __syncthreads();
    #pragma unroll
    for (int d = 1; d < 128; d <<= 1) {
        int t = (tid >= d) ? tmp[tid - d] : 0;
        __syncthreads();
        tmp[tid] += t;
        __syncthreads();
    }
    if (tid < NB_SCAN) g_boff[tid] = tmp[tid] - v;
}

// -------- K2c: globalize offsets; init cursors --------
__global__ void kscanC(int E) {
    int i = blockIdx.x * blockDim.x + threadIdx.x;
    int stride = gridDim.x * blockDim.x;
    for (int j = i; j < NN; j += stride) {
        int off = g_off[j] + g_boff[j >> 9];
        g_off[j] = off;
        g_cur[j] = off;
    }
    if (i == 0) g_off[NN] = E;
}

// -------- K3: counting-sort scatter by dst --------
__global__ void k_scatter(const int* __restrict__ src, const int* __restrict__ dst,
                          const int* __restrict__ et, int E) {
    int i = blockIdx.x * blockDim.x + threadIdx.x;
    int stride = gridDim.x * blockDim.x;
    int n4 = E >> 2;
    const int4* s4 = (const int4*)src;
    const int4* d4 = (const int4*)dst;
    const int4* t4 = (const int4*)et;
    for (int j = i; j < n4; j += stride) {
        int4 s = s4[j];
        int4 d = d4[j];
        int4 t = t4[j];
        int p0 = atomicAdd(&g_cur[d.x], 1);
        int p1 = atomicAdd(&g_cur[d.y], 1);
        int p2 = atomicAdd(&g_cur[d.z], 1);
        int p3 = atomicAdd(&g_cur[d.w], 1);
        g_key[p0] = (unsigned)s.x | ((unsigned)t.x << 16);
        g_key[p1] = (unsigned)s.y | ((unsigned)t.y << 16);
        g_key[p2] = (unsigned)s.z | ((unsigned)t.z << 16);
        g_key[p3] = (unsigned)s.w | ((unsigned)t.w << 16);
    }
    if (i < (E & 3)) {
        int e = (n4 << 2) + i;
        int p = atomicAdd(&g_cur[dst[e]], 1);
        g_key[p] = (unsigned)src[e] | ((unsigned)et[e] << 16);
    }
}

// -------- K4: per-dst aggregation (warp/node, clean 2-edge unroll) --------
__global__ __launch_bounds__(256) void k_agg(const float* __restrict__ feat) {
    int w = (blockIdx.x * 256 + threadIdx.x) >> 5;
    if (w >= NN) return;
    int lane = threadIdx.x & 31;
    int beg = g_off[w], end = g_off[w + 1];
    if (lane == 0) g_cnt[w] = 0;      // re-zero for next replay (deterministic)

    const float2* f2  = (const float2*)feat;
    const float4* rr4 = (const float4*)g_rr;

    float ax0 = 0.f, ay0 = 0.f, bx0 = 0.f, by0 = 0.f, cx0 = 0.f, cy0 = 0.f;
    float ax1 = 0.f, ay1 = 0.f, bx1 = 0.f, by1 = 0.f, cx1 = 0.f, cy1 = 0.f;

    int i = beg;
    if ((end - beg) & 1) {                        // peel odd edge: loop below is pure pairs
        unsigned k = g_key[i++];
        float2 h = f2[(k & 0xffffu) * 32 + lane];
        float4 q = rr4[(k >> 16) * 32 + lane];
        ax0 += h.x;  ay0 += h.y;
        bx0 = fmaf(h.x, q.x, bx0);
        by0 = fmaf(h.y, q.y, by0);
        cx0 += q.z;  cy0 += q.w;
    }
    if (i < end) {
        unsigned k0 = g_key[i];
        unsigned k1 = g_key[i + 1];
        for (; i < end; i += 2) {
            bool more = (i + 2) < end;            // pairs: i+2 < end  =>  i+3 valid
            unsigned n0 = more ? g_key[i + 2] : k0;
            unsigned n1 = more ? g_key[i + 3] : k1;

            float2 h0 = f2[(k0 & 0xffffu) * 32 + lane];
            float4 q0 = rr4[(k0 >> 16) * 32 + lane];
            float2 h1 = f2[(k1 & 0xffffu) * 32 + lane];
            float4 q1 = rr4[(k1 >> 16) * 32 + lane];

            ax0 += h0.x;  ay0 += h0.y;
            bx0 = fmaf(h0.x, q0.x, bx0);
            by0 = fmaf(h0.y, q0.y, by0);
            cx0 += q0.z;  cy0 += q0.w;

            ax1 += h1.x;  ay1 += h1.y;
            bx1 = fmaf(h1.x, q1.x, bx1);
            by1 = fmaf(h1.y, q1.y, by1);
            cx1 += q1.z;  cy1 += q1.w;

            k0 = n0; k1 = n1;
        }
    }

    float inv = 1.0f / fmaxf((float)(end - beg), 1.0f);
    int o = w * 32 + lane;
    ((float2*)g_A)[o] = make_float2((ax0 + ax1) * inv, (ay0 + ay1) * inv);
    ((float2*)g_B)[o] = make_float2((bx0 + bx1) * inv, (by0 + by1) * inv);
    ((float2*)g_C)[o] = make_float2((cx0 + cx1) * inv, (cy0 + cy1) * inv);
}

// -------- K5: out = A@W13 + B@W2 + C + feat@LW  (32 nodes / block, 256 thr) --------
#define TS 65
#define FSMEM ((3 * 4096 + 3 * 32 * TS) * 4)

__global__ __launch_bounds__(256) void k_final(const float* __restrict__ feat,
                                               const float* __restrict__ Wn,
                                               const float* __restrict__ LW,
                                               float* __restrict__ out, int N) {
    extern __shared__ float smem[];
    float* W13s = smem;                 // 4096
    float* W2s  = smem + 4096;          // 4096
    float* LWs  = smem + 8192;          // 4096
    float* As   = smem + 12288;         // 32*65
    float* Bs   = As + 32 * TS;
    float* Fs   = Bs + 32 * TS;

    int tid = threadIdx.x;
    for (int idx = tid; idx < 4096; idx += 256) {
        W13s[idx] = Wn[idx] + Wn[8192 + idx];
        W2s[idx]  = Wn[4096 + idx];
        LWs[idx]  = LW[idx];
    }

    int n0 = blockIdx.x * 32;
    #pragma unroll
    for (int p = 0; p < 6; p++) {
        int idx = p * 256 + tid;        // 0..1535 : matrix = idx/512, slot = idx%512
        int mat = idx >> 9;
        int slot = idx & 511;
        int e = slot >> 4, c4 = slot & 15;
        int node = n0 + e;
        const float* srcp = (mat == 0) ? g_A : (mat == 1) ? g_B : feat;
        float* dstp = (mat == 0) ? As : (mat == 1) ? Bs : Fs;
        float4 v = make_float4(0.f, 0.f, 0.f, 0.f);
        if (node < N) v = *(const float4*)&srcp[(size_t)node * 64 + c4 * 4];
        float* hp = &dstp[e * TS + c4 * 4];
        hp[0] = v.x; hp[1] = v.y; hp[2] = v.z; hp[3] = v.w;
    }
    __syncthreads();

    int ty = tid >> 3, tx = tid & 7, jj = tx * 8;
    int node = n0 + ty;

    unsigned long long a0 = 0, a1 = 0, a2 = 0, a3 = 0;
    #pragma unroll 4
    for (int k = 0; k < 64; k++) {
        float la = As[ty * TS + k];
        float lb = Bs[ty * TS + k];
        float lf = Fs[ty * TS + k];
        unsigned long long la2, lb2, lf2;
        PACK_DUP(la2, la); PACK_DUP(lb2, lb); PACK_DUP(lf2, lf);

        const float* w13 = &W13s[(k << 6) + jj];
        const float* w2  = &W2s[(k << 6) + jj];
        const float* lw  = &LWs[(k << 6) + jj];
        ulonglong2 wA = *reinterpret_cast<const ulonglong2*>(w13);
        ulonglong2 wB = *reinterpret_cast<const ulonglong2*>(w13 + 4);
        ulonglong2 vA = *reinterpret_cast<const ulonglong2*>(w2);
        ulonglong2 vB = *reinterpret_cast<const ulonglong2*>(w2 + 4);
        ulonglong2 uA = *reinterpret_cast<const ulonglong2*>(lw);
        ulonglong2 uB = *reinterpret_cast<const ulonglong2*>(lw + 4);

        FMA2(a0, la2, wA.x); FMA2(a1, la2, wA.y); FMA2(a2, la2, wB.x); FMA2(a3, la2, wB.y);
        FMA2(a0, lb2, vA.x); FMA2(a1, lb2, vA.y); FMA2(a2, lb2, vB.x); FMA2(a3, lb2, vB.y);
        FMA2(a0, lf2, uA.x); FMA2(a1, lf2, uA.y); FMA2(a2, lf2, uB.x); FMA2(a3, lf2, uB.y);
    }

    if (node < N) {
        float4 c0 = *(const float4*)&g_C[(size_t)node * 64 + jj];
        float4 c1 = *(const float4*)&g_C[(size_t)node * 64 + jj + 4];
        float v0, v1, v2, v3, v4, v5, v6, v7;
        UNPACK2(v0, v1, a0); UNPACK2(v2, v3, a1);
        UNPACK2(v4, v5, a2); UNPACK2(v6, v7, a3);
        float* p = out + (size_t)node * 64 + jj;
        *(float4*)p       = make_float4(v0 + c0.x, v1 + c0.y, v2 + c0.z, v3 + c0.w);
        *(float4*)(p + 4) = make_float4(v4 + c1.x, v5 + c1.y, v6 + c1.z, v7 + c1.w);
    }
}

// -------- launch --------
extern "C" void kernel_launch(void* const* d_in, const int* in_sizes, int n_in,
                              void* d_out, int out_size) {
    const float* feat = (const float*)d_in[0];
    const float* rel  = (const float*)d_in[1];
    const float* Wn   = (const float*)d_in[2];
    const float* LW   = (const float*)d_in[3];
    const int*   src  = (const int*)d_in[4];
    const int*   dst  = (const int*)d_in[5];
    const int*   et   = (const int*)d_in[6];
    float* out = (float*)d_out;

    int E = in_sizes[4];
    int N = in_sizes[0] / 64;

    cudaFuncSetAttribute(k_final, cudaFuncAttributeMaxDynamicSharedMemorySize, FSMEM);

    k_fused<<<512, 256>>>(rel, Wn, dst, E);          // 0
    kscanA<<<NB_SCAN, 512>>>();                       // 1
    kscanB<<<1, 128>>>();                             // 2
    kscanC<<<64, 256>>>(E);                           // 3  <- ncu capture slot
    k_scatter<<<800, 256>>>(src, dst, et, E);         // 4
    k_agg<<<(NN * 32 + 255) / 256, 256>>>(feat);      // 5
    k_final<<<(N + 31) / 32, 256, FSMEM>>>(feat, Wn, LW, out, N);
}